// round 17
// baseline (speedup 1.0000x reference)
#include <cuda_runtime.h>

#define NRAD  16
#define NOUT  144            // 16*(1 + 2*4)
#define L35   35
#define MAXE   100000
#define MAXNAT 4096
#define APB    4             // atoms per block
#define MBLOCK 256           // 8 warps = 4 atoms x 2 kg-half warps

__device__ int   g_segstart[MAXNAT + 1];
__device__ float g_gT[(size_t)MAXE * 40];   // [e][k] plain order, k 35..39 = 0

typedef unsigned long long ull;

__device__ __forceinline__ ull pack2(float x, float y) {
    ull r; asm("mov.b64 %0, {%1, %2};" : "=l"(r) : "f"(x), "f"(y)); return r;
}
__device__ __forceinline__ ull dup2(float x) {
    ull r; asm("mov.b64 %0, {%1, %1};" : "=l"(r) : "f"(x)); return r;
}
__device__ __forceinline__ void unpack2(ull p, float& x, float& y) {
    asm("mov.b64 {%0, %1}, %2;" : "=f"(x), "=f"(y) : "l"(p));
}
__device__ __forceinline__ void fma2(ull& d, ull a, ull b) {
    asm("fma.rn.f32x2 %0, %1, %2, %0;" : "+l"(d) : "l"(a), "l"(b));
}

// Prepass: monomials (plain k order, smem-staged coalesced out) + segstarts.
__global__ __launch_bounds__(256)
void prep_kernel(const float* __restrict__ rij, const int* __restrict__ fidx,
                 int E, int nat)
{
    __shared__ float sg[256][40];

    constexpr int LXc[L35] = {0, 0,0,1, 0,0,0,1,1,2,
                              0,0,0,0,1,1,1,2,2,3,
                              0,0,0,0,0,1,1,1,1,2,2,2,3,3,4};
    constexpr int LYc[L35] = {0, 0,1,0, 0,1,2,0,1,0,
                              0,1,2,3,0,1,2,0,1,0,
                              0,1,2,3,4,0,1,2,3,0,1,2,0,1,0};
    constexpr int LZc[L35] = {0, 1,0,0, 2,1,0,1,0,0,
                              3,2,1,0,2,1,0,1,0,0,
                              4,3,2,1,0,3,2,1,0,2,1,0,1,0,0};
    constexpr float FNc[L35] = {1.f, 1.f,1.f,1.f,
                                1.f,2.f,1.f,2.f,2.f,1.f,
                                1.f,3.f,3.f,1.f,3.f,6.f,3.f,3.f,3.f,1.f,
                                1.f,4.f,6.f,4.f,1.f,4.f,12.f,12.f,4.f,
                                6.f,12.f,6.f,4.f,4.f,1.f};

    const int tid = threadIdx.x;
    const int e0  = blockIdx.x * 256;
    const int e   = e0 + tid;
    const int cnt = min(256, E - e0);

    if (e < E) {
        int cur  = fidx[e];
        int prev = (e == 0) ? -1 : fidx[e - 1];
        for (int a = prev + 1; a <= cur; a++) g_segstart[a] = e;
        if (e == E - 1)
            for (int a = cur + 1; a <= nat; a++) g_segstart[a] = E;

        float x = rij[e*3+0], y = rij[e*3+1], z = rij[e*3+2];
        float px[5], py[5], pz[5];
        px[0]=1.f; px[1]=x; px[2]=x*x; px[3]=px[2]*x; px[4]=px[2]*px[2];
        py[0]=1.f; py[1]=y; py[2]=y*y; py[3]=py[2]*y; py[4]=py[2]*py[2];
        pz[0]=1.f; pz[1]=z; pz[2]=z*z; pz[3]=pz[2]*z; pz[4]=pz[2]*pz[2];
        #pragma unroll
        for (int k = 0; k < L35; k++)
            sg[tid][k] = FNc[k] * px[LXc[k]] * py[LYc[k]] * pz[LZc[k]];
        #pragma unroll
        for (int k = L35; k < 40; k++) sg[tid][k] = 0.f;
    }
    __syncthreads();

    float4*       dst = (float4*)g_gT + (size_t)e0 * 10;
    const float4* src = (const float4*)sg;
    for (int i = tid; i < cnt * 10; i += 256)
        dst[i] = src[i];
}

__global__ __launch_bounds__(MBLOCK, 3)
void mbp_main(const float* __restrict__ radial,   // [E,16,5]
              const float* __restrict__ lamw,     // [2]
              float* __restrict__ out,            // [nat, NOUT]
              int nat)
{
    // kg1 warp's partials: [atom-in-block][j][chh][c2][l]
    __shared__ float s_p[APB][NRAD][2][2][2];

    const int lane = threadIdx.x & 31;
    const int warp = threadIdx.x >> 5;
    const int ab   = warp >> 1;          // atom within block
    const int kg   = warp & 1;           // k-half: 0 -> k0..19, 1 -> k20..39
    const int j    = lane & 15;
    const int chh  = lane >> 4;          // channel half: ch = chh*2 + c2
    const int a    = blockIdx.x * APB + ab;
    const bool ok  = (a < nat);

    const int start = ok ? g_segstart[a]     : 0;
    const int end   = ok ? g_segstart[a + 1] : 0;

    // acc[i][c2]: k-pair (2i,2i+1) of this warp's k-half, channel chh*2+c2
    ull acc[10][2];
    #pragma unroll
    for (int i = 0; i < 10; i++) { acc[i][0] = 0ull; acc[i][1] = 0ull; }
    float accR = 0.f;

    const float*  rp = radial + (size_t)start * 80 + j * 5 + chh * 2;
    const float4* gp = (const float4*)g_gT + (size_t)start * 10 + kg * 5;

    #pragma unroll 8
    for (int e = start; e < end; e++) {
        float4 G0 = gp[0], G1 = gp[1], G2 = gp[2], G3 = gp[3], G4 = gp[4];
        float ra = rp[0], rb = rp[1];
        if (kg == 0 && chh == 1) accR += rp[2];   // ch4 = j*5+4 = base+2 when chh=1
        rp += 80;  gp += 10;
        ull da = dup2(ra), db = dup2(rb);
        ull g0 = pack2(G0.x, G0.y), g1 = pack2(G0.z, G0.w);
        ull g2 = pack2(G1.x, G1.y), g3 = pack2(G1.z, G1.w);
        ull g4 = pack2(G2.x, G2.y), g5 = pack2(G2.z, G2.w);
        ull g6 = pack2(G3.x, G3.y), g7 = pack2(G3.z, G3.w);
        ull g8 = pack2(G4.x, G4.y), g9 = pack2(G4.z, G4.w);
        fma2(acc[0][0], g0, da);  fma2(acc[0][1], g0, db);
        fma2(acc[1][0], g1, da);  fma2(acc[1][1], g1, db);
        fma2(acc[2][0], g2, da);  fma2(acc[2][1], g2, db);
        fma2(acc[3][0], g3, da);  fma2(acc[3][1], g3, db);
        fma2(acc[4][0], g4, da);  fma2(acc[4][1], g4, db);
        fma2(acc[5][0], g5, da);  fma2(acc[5][1], g5, db);
        fma2(acc[6][0], g6, da);  fma2(acc[6][1], g6, db);
        fma2(acc[7][0], g7, da);  fma2(acc[7][1], g7, db);
        fma2(acc[8][0], g8, da);  fma2(acc[8][1], g8, db);
        fma2(acc[9][0], g9, da);  fma2(acc[9][1], g9, db);
    }

    // ---- group squares by lambda exponent ----
    // kg0 (k0..19) exponents: k0:0, k1-3:1, k4-9:2, k10-19:3
    // kg1 (k20..39): k20-34 exponent 4, k35-39 zero pads (group 0, harmless)
    float p[2][2];     // [c2][l]
    float l0 = lamw[0], l1 = lamw[1];
    if (kg == 0) {
        constexpr int GRP[20] = {0,1,1,1,2,2,2,2,2,2,3,3,3,3,3,3,3,3,3,3};
        float gs[4][2] = {{0,0},{0,0},{0,0},{0,0}};
        #pragma unroll
        for (int i = 0; i < 10; i++)
            #pragma unroll
            for (int c2 = 0; c2 < 2; c2++) {
                float u, v; unpack2(acc[i][c2], u, v);
                gs[GRP[2*i]][c2]   += u * u;
                gs[GRP[2*i+1]][c2] += v * v;
            }
        float l0b = l0*l0, l0c = l0b*l0;
        float l1b = l1*l1, l1c = l1b*l1;
        #pragma unroll
        for (int c2 = 0; c2 < 2; c2++) {
            p[c2][0] = gs[0][c2] + gs[1][c2]*l0 + gs[2][c2]*l0b + gs[3][c2]*l0c;
            p[c2][1] = gs[0][c2] + gs[1][c2]*l1 + gs[2][c2]*l1b + gs[3][c2]*l1c;
        }
    } else {
        float gs[2] = {0, 0};
        #pragma unroll
        for (int i = 0; i < 10; i++)
            #pragma unroll
            for (int c2 = 0; c2 < 2; c2++) {
                float u, v; unpack2(acc[i][c2], u, v);
                gs[c2] += u * u + v * v;
            }
        float l0d = (l0*l0)*(l0*l0);
        float l1d = (l1*l1)*(l1*l1);
        #pragma unroll
        for (int c2 = 0; c2 < 2; c2++) {
            p[c2][0] = gs[c2] * l0d;
            p[c2][1] = gs[c2] * l1d;
        }
    }

    // ---- merge the two kg warps via smem ----
    if (kg == 1) {
        #pragma unroll
        for (int c2 = 0; c2 < 2; c2++) {
            s_p[ab][j][chh][c2][0] = p[c2][0];
            s_p[ab][j][chh][c2][1] = p[c2][1];
        }
    } else if (chh == 1 && ok) {
        out[(size_t)a * NOUT + j] = accR;    // two-body column, direct
    }
    __syncthreads();

    if (kg == 0 && ok) {
        float* orow = out + (size_t)a * NOUT;
        #pragma unroll
        for (int c2 = 0; c2 < 2; c2++) {
            int c = chh * 2 + c2;
            float scale = __int_as_float(0x3F800000 - (c << 23));   // 2^-c
            orow[16 + c*32 + j*2 + 0] = (p[c2][0] + s_p[ab][j][chh][c2][0]) * scale;
            orow[16 + c*32 + j*2 + 1] = (p[c2][1] + s_p[ab][j][chh][c2][1]) * scale;
        }
    }
}

extern "C" void kernel_launch(void* const* d_in, const int* in_sizes, int n_in,
                              void* d_out, int out_size)
{
    const float* rij    = (const float*)d_in[0];   // [E,3]
    const float* radial = (const float*)d_in[1];   // [E,16,5]
    const float* lamw   = (const float*)d_in[2];   // [2]
    const int*   fidx   = (const int*)  d_in[4];   // [E] sorted

    const int E   = in_sizes[0] / 3;
    const int nat = out_size / NOUT;

    prep_kernel<<<(E + 255) / 256, 256>>>(rij, fidx, E, nat);
    mbp_main<<<(nat + APB - 1) / APB, MBLOCK>>>(radial, lamw, (float*)d_out, nat);
}